// round 10
// baseline (speedup 1.0000x reference)
#include <cuda_runtime.h>
#include <cuda_fp16.h>
#include <cstdint>

#define NHEADS   8
#define DH       64
#define TSEQ     2048
#define BATCH    4
#define HIDDEN   256
#define DMODEL   (NHEADS * DH)      // 512
#define NTOK     (TSEQ * BATCH)     // 8192
#define SCALING  0.125f
#define LOG2E    1.4426950408889634f

// ---------------- device scratch ----------------
__device__ __half g_w1h[3][DH * HIDDEN];
__device__ __half g_w2h[3][HIDDEN * DMODEL];
__device__ __half g_woh[DMODEL * DH];
__device__ __half g_hid[3][NTOK * HIDDEN];
__device__ __half g_q[BATCH * NHEADS * TSEQ * DH];   // [b,h,t,d], q pre-scaled
__device__ __half g_k[BATCH * NHEADS * TSEQ * DH];
__device__ __half g_v[BATCH * NHEADS * TSEQ * DH];
__device__ __half g_ao[NTOK * DMODEL];               // [t*B+b][h*64+d]

// ======================= PTX helpers =======================
__device__ __forceinline__ void ldsm4(uint32_t& r0, uint32_t& r1, uint32_t& r2, uint32_t& r3, const void* p) {
    uint32_t a = (uint32_t)__cvta_generic_to_shared(p);
    asm volatile("ldmatrix.sync.aligned.m8n8.x4.shared.b16 {%0,%1,%2,%3}, [%4];"
                 : "=r"(r0), "=r"(r1), "=r"(r2), "=r"(r3) : "r"(a));
}
__device__ __forceinline__ void ldsm4t(uint32_t& r0, uint32_t& r1, uint32_t& r2, uint32_t& r3, const void* p) {
    uint32_t a = (uint32_t)__cvta_generic_to_shared(p);
    asm volatile("ldmatrix.sync.aligned.m8n8.x4.trans.shared.b16 {%0,%1,%2,%3}, [%4];"
                 : "=r"(r0), "=r"(r1), "=r"(r2), "=r"(r3) : "r"(a));
}
__device__ __forceinline__ void mma16816(float* c, const uint32_t* a, uint32_t b0, uint32_t b1) {
    asm volatile("mma.sync.aligned.m16n8k16.row.col.f32.f16.f16.f32 "
                 "{%0,%1,%2,%3}, {%4,%5,%6,%7}, {%8,%9}, {%0,%1,%2,%3};"
                 : "+f"(c[0]), "+f"(c[1]), "+f"(c[2]), "+f"(c[3])
                 : "r"(a[0]), "r"(a[1]), "r"(a[2]), "r"(a[3]), "r"(b0), "r"(b1));
}
__device__ __forceinline__ float ex2(float x) {
    float r; asm("ex2.approx.ftz.f32 %0, %1;" : "=f"(r) : "f"(x)); return r;
}
__device__ __forceinline__ void cpa16(void* dst, const void* src) {
    asm volatile("cp.async.cg.shared.global [%0], [%1], 16;"
                 :: "r"((uint32_t)__cvta_generic_to_shared(dst)), "l"(src));
}
__device__ __forceinline__ uint32_t h2u(__half2 v) {
    return *reinterpret_cast<uint32_t*>(&v);
}

// =====================================================================
// Weight pre-conversion (fp32 -> fp16), once per launch
// =====================================================================
__global__ __launch_bounds__(256) void convert_w_kernel(
        const float* __restrict__ Wq1, const float* __restrict__ Wk1, const float* __restrict__ Wv1,
        const float* __restrict__ Wq2, const float* __restrict__ Wk2, const float* __restrict__ Wv2,
        const float* __restrict__ Wo) {
    const int tid = blockIdx.x * blockDim.x + threadIdx.x;
    const int stride = gridDim.x * blockDim.x;
    const int N1 = DH * HIDDEN;
    const int N2 = HIDDEN * DMODEL;
    for (int i = tid; i < 3 * N1; i += stride) {
        int z = i / N1, j = i - z * N1;
        const float* s = (z == 0) ? Wq1 : (z == 1) ? Wk1 : Wv1;
        g_w1h[z][j] = __float2half(s[j]);
    }
    for (int i = tid; i < 3 * N2; i += stride) {
        int z = i / N2, j = i - z * N2;
        const float* s = (z == 0) ? Wq2 : (z == 1) ? Wk2 : Wv2;
        g_w2h[z][j] = __float2half(s[j]);
    }
    for (int i = tid; i < DMODEL * DH; i += stride)
        g_woh[i] = __float2half(Wo[i]);
}

// =====================================================================
// MLP stage 1: H = relu(X @ W1 + b1)
// =====================================================================
__global__ __launch_bounds__(256) void mlp1_kernel(
        const float* __restrict__ Xq, const float* __restrict__ Xk, const float* __restrict__ Xv,
        const float* __restrict__ bq, const float* __restrict__ bk, const float* __restrict__ bv) {
    __shared__ __half Xs[128][72];
    __shared__ __half Ws[2][64][72];
    const int tid = threadIdx.x, lane = tid & 31, w = tid >> 5;
    const int my = w & 3, wx = w >> 2;
    const int n0 = blockIdx.x * 128, m0 = blockIdx.y * 128, z = blockIdx.z;
    const float* X    = (z == 0) ? Xq : (z == 1) ? Xk : Xv;
    const float* bias = (z == 0) ? bq : (z == 1) ? bk : bv;

    for (int idx = tid; idx < 1024; idx += 256) {
        int r = idx >> 3, c8 = idx & 7;
        const float4* src = (const float4*)(X + (size_t)(m0 + r) * DH + c8 * 8);
        float4 f0 = src[0], f1 = src[1];
        uint4 u;
        u.x = h2u(__floats2half2_rn(f0.x, f0.y));
        u.y = h2u(__floats2half2_rn(f0.z, f0.w));
        u.z = h2u(__floats2half2_rn(f1.x, f1.y));
        u.w = h2u(__floats2half2_rn(f1.z, f1.w));
        *(uint4*)&Xs[r][c8 * 8] = u;
    }
    for (int idx = tid; idx < 1024; idx += 256) {
        int r = idx >> 4, c8 = idx & 15;
        *(uint4*)&Ws[c8 >> 3][r][(c8 & 7) * 8] =
            *(const uint4*)(g_w1h[z] + (size_t)r * HIDDEN + n0 + c8 * 8);
    }
    __syncthreads();

    float acc[2][8][4];
    #pragma unroll
    for (int i = 0; i < 2; i++)
        #pragma unroll
        for (int j = 0; j < 8; j++)
            acc[i][j][0] = acc[i][j][1] = acc[i][j][2] = acc[i][j][3] = 0.0f;

    #pragma unroll
    for (int kk = 0; kk < 4; kk++) {
        uint32_t a[2][4];
        #pragma unroll
        for (int i = 0; i < 2; i++)
            ldsm4(a[i][0], a[i][1], a[i][2], a[i][3],
                  &Xs[my * 32 + i * 16 + (lane & 15)][kk * 16 + 8 * (lane >> 4)]);
        #pragma unroll
        for (int ng = 0; ng < 4; ng++) {
            uint32_t v0, v1, v2, v3;
            ldsm4t(v0, v1, v2, v3,
                   &Ws[wx][kk * 16 + (lane & 7) + 8 * ((lane >> 3) & 1)][ng * 16 + 8 * (lane >> 4)]);
            #pragma unroll
            for (int i = 0; i < 2; i++) {
                mma16816(acc[i][2 * ng],     a[i], v0, v1);
                mma16816(acc[i][2 * ng + 1], a[i], v2, v3);
            }
        }
    }

    const int colbase = n0 + wx * 64;
    #pragma unroll
    for (int j = 0; j < 8; j++) {
        int col = colbase + j * 8 + 2 * (lane & 3);
        float b0 = bias[col], b1 = bias[col + 1];
        #pragma unroll
        for (int i = 0; i < 2; i++) {
            int row = m0 + my * 32 + i * 16 + (lane >> 2);
            *(__half2*)&g_hid[z][(size_t)row * HIDDEN + col] =
                __floats2half2_rn(fmaxf(acc[i][j][0] + b0, 0.f), fmaxf(acc[i][j][1] + b1, 0.f));
            *(__half2*)&g_hid[z][(size_t)(row + 8) * HIDDEN + col] =
                __floats2half2_rn(fmaxf(acc[i][j][2] + b0, 0.f), fmaxf(acc[i][j][3] + b1, 0.f));
        }
    }
}

// =====================================================================
// MLP stage 2: OUT = (H @ W2 + b2) * scale -> [b,h,t,d]
// =====================================================================
__global__ __launch_bounds__(256) void mlp2_kernel(
        const float* __restrict__ bq, const float* __restrict__ bk, const float* __restrict__ bv) {
    extern __shared__ char dynsm[];
    __half (*As)[128][72]    = (__half(*)[128][72])dynsm;
    __half (*Ws)[2][64][72]  = (__half(*)[2][64][72])(dynsm + 36864);
    const int tid = threadIdx.x, lane = tid & 31, w = tid >> 5;
    const int my = w & 3, wx = w >> 2;
    const int nb = blockIdx.x, m0 = blockIdx.y * 128, z = blockIdx.z;
    const float* bias  = (z == 0) ? bq : (z == 1) ? bk : bv;
    const float scale  = (z == 0) ? SCALING : 1.0f;
    const __half* Hsrc = g_hid[z];
    const __half* Wsrc = g_w2h[z];
    const int n0 = nb * 128;

    auto issue = [&](int st, int kc) {
        for (int idx = tid; idx < 1024; idx += 256) {
            int r = idx >> 3, c8 = idx & 7;
            cpa16(&As[st][r][c8 * 8], Hsrc + (size_t)(m0 + r) * HIDDEN + kc * 64 + c8 * 8);
        }
        for (int idx = tid; idx < 1024; idx += 256) {
            int r = idx >> 4, c8 = idx & 15;
            cpa16(&Ws[st][c8 >> 3][r][(c8 & 7) * 8],
                  Wsrc + (size_t)(kc * 64 + r) * DMODEL + n0 + c8 * 8);
        }
        asm volatile("cp.async.commit_group;");
    };

    issue(0, 0);

    float acc[2][8][4];
    #pragma unroll
    for (int i = 0; i < 2; i++)
        #pragma unroll
        for (int j = 0; j < 8; j++)
            acc[i][j][0] = acc[i][j][1] = acc[i][j][2] = acc[i][j][3] = 0.0f;

    for (int kc = 0; kc < 4; kc++) {
        asm volatile("cp.async.wait_group 0;");
        __syncthreads();
        if (kc + 1 < 4) issue((kc + 1) & 1, kc + 1);
        const int cur = kc & 1;
        #pragma unroll
        for (int kk = 0; kk < 4; kk++) {
            uint32_t a[2][4];
            #pragma unroll
            for (int i = 0; i < 2; i++)
                ldsm4(a[i][0], a[i][1], a[i][2], a[i][3],
                      &As[cur][my * 32 + i * 16 + (lane & 15)][kk * 16 + 8 * (lane >> 4)]);
            #pragma unroll
            for (int ng = 0; ng < 4; ng++) {
                uint32_t v0, v1, v2, v3;
                ldsm4t(v0, v1, v2, v3,
                       &Ws[cur][wx][kk * 16 + (lane & 7) + 8 * ((lane >> 3) & 1)][ng * 16 + 8 * (lane >> 4)]);
                #pragma unroll
                for (int i = 0; i < 2; i++) {
                    mma16816(acc[i][2 * ng],     a[i], v0, v1);
                    mma16816(acc[i][2 * ng + 1], a[i], v2, v3);
                }
            }
        }
        __syncthreads();
    }

    __half* dst = (z == 0) ? g_q : (z == 1) ? g_k : g_v;
    const int colbase = n0 + wx * 64;
    #pragma unroll
    for (int j = 0; j < 8; j++) {
        int col = colbase + j * 8 + 2 * (lane & 3);
        float b0 = bias[col], b1 = bias[col + 1];
        int h = col >> 6, d = col & 63;
        #pragma unroll
        for (int i = 0; i < 2; i++) {
            #pragma unroll
            for (int half_ = 0; half_ < 2; half_++) {
                int row = m0 + my * 32 + i * 16 + (lane >> 2) + half_ * 8;
                int t = row >> 2, b = row & 3;
                float v0f = (acc[i][j][2 * half_]     + b0) * scale;
                float v1f = (acc[i][j][2 * half_ + 1] + b1) * scale;
                *(__half2*)&dst[(((size_t)(b * NHEADS + h)) * TSEQ + t) * DH + d] =
                    __floats2half2_rn(v0f, v1f);
            }
        }
    }
}

// =====================================================================
// Flash attention (R5 design: Br=64, 4 warps, 1 strip/warp) with
// DYNAMIC smem so 3 CTAs/SM fit (static smem was capped by carveout).
// grid = (8 heads, 32 t-tiles, 4 batch), smem 46080 B.
// =====================================================================
#define ATTN_SMEM 46080

__global__ __launch_bounds__(128, 3) void attn_kernel(const float* __restrict__ mask) {
    extern __shared__ char sm[];
    __half (*Qs)[72]     = (__half(*)[72])sm;                 // 64x72 = 9216
    __half (*Ks)[64][72] = (__half(*)[64][72])(sm + 9216);    // 2x64x72 = 18432
    __half (*Vs)[64][72] = (__half(*)[64][72])(sm + 27648);   // 2x64x72 = 18432

    const int tid  = threadIdx.x;
    const int lane = tid & 31;
    const int w    = tid >> 5;
    const int h    = blockIdx.x;
    const int t0   = blockIdx.y * 64;
    const int b    = blockIdx.z;

    const __half* qbase = g_q + ((size_t)(b * NHEADS + h) * TSEQ + t0) * DH;
    const __half* kbase = g_k + (size_t)(b * NHEADS + h) * TSEQ * DH;
    const __half* vbase = g_v + (size_t)(b * NHEADS + h) * TSEQ * DH;

    for (int i = tid; i < 64 * 8; i += 128) {
        int r = i >> 3, c = i & 7;
        *(uint4*)&Qs[r][c * 8] = ((const uint4*)qbase)[i];
    }
    for (int i = tid; i < 512; i += 128) {
        int r = i >> 3, c = i & 7;
        cpa16(&Ks[0][r][c * 8], kbase + r * 64 + c * 8);
        cpa16(&Vs[0][r][c * 8], vbase + r * 64 + c * 8);
    }
    asm volatile("cp.async.commit_group;");
    __syncthreads();

    uint32_t qa[4][4];
    #pragma unroll
    for (int kk = 0; kk < 4; kk++)
        ldsm4(qa[kk][0], qa[kk][1], qa[kk][2], qa[kk][3],
              &Qs[w * 16 + (lane & 15)][kk * 16 + 8 * (lane >> 4)]);

    float Oa[8][4];
    #pragma unroll
    for (int j = 0; j < 8; j++) { Oa[j][0] = Oa[j][1] = Oa[j][2] = Oa[j][3] = 0.0f; }
    float m0 = -1e30f, m1 = -1e30f, l0 = 0.0f, l1 = 0.0f;

    const float* mrow = mask + ((size_t)b * TSEQ + (t0 + w * 16 + (lane >> 2))) * TSEQ + 2 * (lane & 3);

    for (int it = 0; it < 32; ++it) {
        const int s0 = it * 64;
        const int cur = it & 1;
        asm volatile("cp.async.wait_group 0;");
        __syncthreads();
        if (it + 1 < 32) {
            const __half* kg = kbase + (size_t)(s0 + 64) * 64;
            const __half* vg = vbase + (size_t)(s0 + 64) * 64;
            const int nxt = cur ^ 1;
            for (int i = tid; i < 512; i += 128) {
                int r = i >> 3, c = i & 7;
                cpa16(&Ks[nxt][r][c * 8], kg + r * 64 + c * 8);
                cpa16(&Vs[nxt][r][c * 8], vg + r * 64 + c * 8);
            }
            asm volatile("cp.async.commit_group;");
        }

        float2 mk0[8], mk1[8];
        #pragma unroll
        for (int j = 0; j < 8; j++) {
            mk0[j] = *(const float2*)(mrow + s0 + j * 8);
            mk1[j] = *(const float2*)(mrow + 8 * TSEQ + s0 + j * 8);
        }

        float Sa[8][4];
        #pragma unroll
        for (int j = 0; j < 8; j++) { Sa[j][0] = Sa[j][1] = Sa[j][2] = Sa[j][3] = 0.0f; }
        #pragma unroll
        for (int ng = 0; ng < 4; ng++) {
            #pragma unroll
            for (int kk = 0; kk < 4; kk++) {
                uint32_t k0, k1, k2, k3;
                ldsm4(k0, k1, k2, k3, &Ks[cur][ng * 16 + (lane & 15)][kk * 16 + 8 * (lane >> 4)]);
                mma16816(Sa[2 * ng],     qa[kk], k0, k2);
                mma16816(Sa[2 * ng + 1], qa[kk], k1, k3);
            }
        }

        float mx0 = -1e30f, mx1 = -1e30f;
        #pragma unroll
        for (int j = 0; j < 8; j++) {
            Sa[j][0] += mk0[j].x; Sa[j][1] += mk0[j].y;
            Sa[j][2] += mk1[j].x; Sa[j][3] += mk1[j].y;
            mx0 = fmaxf(mx0, fmaxf(Sa[j][0], Sa[j][1]));
            mx1 = fmaxf(mx1, fmaxf(Sa[j][2], Sa[j][3]));
        }
        mx0 = fmaxf(mx0, __shfl_xor_sync(0xffffffffu, mx0, 1));
        mx0 = fmaxf(mx0, __shfl_xor_sync(0xffffffffu, mx0, 2));
        mx1 = fmaxf(mx1, __shfl_xor_sync(0xffffffffu, mx1, 1));
        mx1 = fmaxf(mx1, __shfl_xor_sync(0xffffffffu, mx1, 2));
        float mn0 = fmaxf(m0, mx0), mn1 = fmaxf(m1, mx1);
        float alpha0 = ex2((m0 - mn0) * LOG2E);
        float alpha1 = ex2((m1 - mn1) * LOG2E);
        m0 = mn0; m1 = mn1;

        float rs0 = 0.0f, rs1 = 0.0f;
        #pragma unroll
        for (int j = 0; j < 8; j++) {
            Sa[j][0] = ex2((Sa[j][0] - mn0) * LOG2E);
            Sa[j][1] = ex2((Sa[j][1] - mn0) * LOG2E);
            Sa[j][2] = ex2((Sa[j][2] - mn1) * LOG2E);
            Sa[j][3] = ex2((Sa[j][3] - mn1) * LOG2E);
            rs0 += Sa[j][0] + Sa[j][1];
            rs1 += Sa[j][2] + Sa[j][3];
        }
        rs0 += __shfl_xor_sync(0xffffffffu, rs0, 1);
        rs0 += __shfl_xor_sync(0xffffffffu, rs0, 2);
        rs1 += __shfl_xor_sync(0xffffffffu, rs1, 1);
        rs1 += __shfl_xor_sync(0xffffffffu, rs1, 2);
        l0 = l0 * alpha0 + rs0;
        l1 = l1 * alpha1 + rs1;

        uint32_t Pa[4][4];
        #pragma unroll
        for (int kk = 0; kk < 4; kk++) {
            Pa[kk][0] = h2u(__floats2half2_rn(Sa[2 * kk][0],     Sa[2 * kk][1]));
            Pa[kk][1] = h2u(__floats2half2_rn(Sa[2 * kk][2],     Sa[2 * kk][3]));
            Pa[kk][2] = h2u(__floats2half2_rn(Sa[2 * kk + 1][0], Sa[2 * kk + 1][1]));
            Pa[kk][3] = h2u(__floats2half2_rn(Sa[2 * kk + 1][2], Sa[2 * kk + 1][3]));
        }

        #pragma unroll
        for (int j = 0; j < 8; j++) {
            Oa[j][0] *= alpha0; Oa[j][1] *= alpha0;
            Oa[j][2] *= alpha1; Oa[j][3] *= alpha1;
        }

        #pragma unroll
        for (int kk = 0; kk < 4; kk++) {
            #pragma unroll
            for (int ng = 0; ng < 4; ng++) {
                uint32_t v0, v1, v2, v3;
                ldsm4t(v0, v1, v2, v3,
                       &Vs[cur][kk * 16 + (lane & 7) + 8 * ((lane >> 3) & 1)][ng * 16 + 8 * (lane >> 4)]);
                mma16816(Oa[2 * ng],     Pa[kk], v0, v1);
                mma16816(Oa[2 * ng + 1], Pa[kk], v2, v3);
            }
        }
    }

    const float inv0 = 1.0f / l0, inv1 = 1.0f / l1;
    const int r0g = t0 + w * 16 + (lane >> 2);
    const int r1g = r0g + 8;
    #pragma unroll
    for (int j = 0; j < 8; j++) {
        int col = h * DH + j * 8 + 2 * (lane & 3);
        __half2* p0 = (__half2*)(g_ao + ((size_t)r0g * BATCH + b) * DMODEL + col);
        __half2* p1 = (__half2*)(g_ao + ((size_t)r1g * BATCH + b) * DMODEL + col);
        *p0 = __floats2half2_rn(Oa[j][0] * inv0, Oa[j][1] * inv0);
        *p1 = __floats2half2_rn(Oa[j][2] * inv1, Oa[j][3] * inv1);
    }
}

// =====================================================================
// Output projection: OUT[8192,64] = AO[8192,512] @ Wo + bo
// =====================================================================
__global__ __launch_bounds__(256) void oproj_kernel(const float* __restrict__ bias,
                                                    float* __restrict__ out) {
    __shared__ __half As[2][64][72];
    __shared__ __half Ws[2][64][72];
    const int tid = threadIdx.x, lane = tid & 31, w = tid >> 5;
    const int my = w & 3, wn = w >> 2;
    const int m0 = blockIdx.x * 64;

    auto issue = [&](int st, int kc) {
        for (int idx = tid; idx < 512; idx += 256) {
            int r = idx >> 3, c8 = idx & 7;
            cpa16(&As[st][r][c8 * 8], g_ao + (size_t)(m0 + r) * DMODEL + kc * 64 + c8 * 8);
        }
        for (int idx = tid; idx < 512; idx += 256) {
            int r = idx >> 3, c8 = idx & 7;
            cpa16(&Ws[st][r][c8 * 8], g_woh + (size_t)(kc * 64 + r) * DH + c8 * 8);
        }
        asm volatile("cp.async.commit_group;");
    };

    issue(0, 0);

    float acc[4][4];
    #pragma unroll
    for (int j = 0; j < 4; j++) acc[j][0] = acc[j][1] = acc[j][2] = acc[j][3] = 0.0f;

    for (int kc = 0; kc < 8; kc++) {
        asm volatile("cp.async.wait_group 0;");
        __syncthreads();
        if (kc + 1 < 8) issue((kc + 1) & 1, kc + 1);
        const int cur = kc & 1;
        #pragma unroll
        for (int kk = 0; kk < 4; kk++) {
            uint32_t a[4];
            ldsm4(a[0], a[1], a[2], a[3],
                  &As[cur][my * 16 + (lane & 15)][kk * 16 + 8 * (lane >> 4)]);
            #pragma unroll
            for (int ng = 0; ng < 2; ng++) {
                uint32_t v0, v1, v2, v3;
                ldsm4t(v0, v1, v2, v3,
                       &Ws[cur][kk * 16 + (lane & 7) + 8 * ((lane >> 3) & 1)][wn * 32 + ng * 16 + 8 * (lane >> 4)]);
                mma16816(acc[2 * ng],     a, v0, v1);
                mma16816(acc[2 * ng + 1], a, v2, v3);
            }
        }
        __syncthreads();
    }

    #pragma unroll
    for (int j = 0; j < 4; j++) {
        int col = wn * 32 + j * 8 + 2 * (lane & 3);
        float b0 = bias[col], b1 = bias[col + 1];
        int row = m0 + my * 16 + (lane >> 2);
        *(float2*)&out[(size_t)row * DH + col]       = make_float2(acc[j][0] + b0, acc[j][1] + b1);
        *(float2*)&out[(size_t)(row + 8) * DH + col] = make_float2(acc[j][2] + b0, acc[j][3] + b1);
    }
}

// =====================================================================
extern "C" void kernel_launch(void* const* d_in, const int* in_sizes, int n_in,
                              void* d_out, int out_size) {
    const float* query = (const float*)d_in[0];
    const float* key   = (const float*)d_in[1];
    const float* value = (const float*)d_in[2];
    const float* amask = (const float*)d_in[3];
    const float* Wq1 = (const float*)d_in[4];
    const float* bq1 = (const float*)d_in[5];
    const float* Wq2 = (const float*)d_in[6];
    const float* bq2 = (const float*)d_in[7];
    const float* Wk1 = (const float*)d_in[8];
    const float* bk1 = (const float*)d_in[9];
    const float* Wk2 = (const float*)d_in[10];
    const float* bk2 = (const float*)d_in[11];
    const float* Wv1 = (const float*)d_in[12];
    const float* bv1 = (const float*)d_in[13];
    const float* Wv2 = (const float*)d_in[14];
    const float* bv2 = (const float*)d_in[15];
    const float* Wo  = (const float*)d_in[16];
    const float* bo  = (const float*)d_in[17];
    float* out = (float*)d_out;

    convert_w_kernel<<<512, 256>>>(Wq1, Wk1, Wv1, Wq2, Wk2, Wv2, Wo);
    mlp1_kernel<<<dim3(2, 64, 3), 256>>>(query, key, value, bq1, bk1, bv1);
    cudaFuncSetAttribute(mlp2_kernel, cudaFuncAttributeMaxDynamicSharedMemorySize, 73728);
    mlp2_kernel<<<dim3(4, 64, 3), 256, 73728>>>(bq2, bk2, bv2);
    cudaFuncSetAttribute(attn_kernel, cudaFuncAttributeMaxDynamicSharedMemorySize, ATTN_SMEM);
    attn_kernel<<<dim3(NHEADS, TSEQ / 64, BATCH), 128, ATTN_SMEM>>>(amask);
    oproj_kernel<<<dim3(128), 256>>>(bo, out);
}

// round 12
// speedup vs baseline: 1.0030x; 1.0030x over previous
#include <cuda_runtime.h>
#include <cuda_fp16.h>
#include <cstdint>

#define NHEADS   8
#define DH       64
#define TSEQ     2048
#define BATCH    4
#define HIDDEN   256
#define DMODEL   (NHEADS * DH)      // 512
#define NTOK     (TSEQ * BATCH)     // 8192
#define SCALING  0.125f
#define LOG2E    1.4426950408889634f

// ---------------- device scratch ----------------
__device__ __half g_w1h[3][DH * HIDDEN];
__device__ __half g_w2h[3][HIDDEN * DMODEL];
__device__ __half g_woh[DMODEL * DH];
__device__ __half g_hid[3][NTOK * HIDDEN];
__device__ __half g_q[BATCH * NHEADS * TSEQ * DH];   // [b,h,t,d], q pre-scaled
__device__ __half g_k[BATCH * NHEADS * TSEQ * DH];
__device__ __half g_v[BATCH * NHEADS * TSEQ * DH];
__device__ __half g_ao[NTOK * DMODEL];               // [t*B+b][h*64+d]

// ======================= PTX helpers =======================
__device__ __forceinline__ void ldsm4(uint32_t& r0, uint32_t& r1, uint32_t& r2, uint32_t& r3, const void* p) {
    uint32_t a = (uint32_t)__cvta_generic_to_shared(p);
    asm volatile("ldmatrix.sync.aligned.m8n8.x4.shared.b16 {%0,%1,%2,%3}, [%4];"
                 : "=r"(r0), "=r"(r1), "=r"(r2), "=r"(r3) : "r"(a));
}
__device__ __forceinline__ void ldsm4t(uint32_t& r0, uint32_t& r1, uint32_t& r2, uint32_t& r3, const void* p) {
    uint32_t a = (uint32_t)__cvta_generic_to_shared(p);
    asm volatile("ldmatrix.sync.aligned.m8n8.x4.trans.shared.b16 {%0,%1,%2,%3}, [%4];"
                 : "=r"(r0), "=r"(r1), "=r"(r2), "=r"(r3) : "r"(a));
}
__device__ __forceinline__ void mma16816(float* c, const uint32_t* a, uint32_t b0, uint32_t b1) {
    asm volatile("mma.sync.aligned.m16n8k16.row.col.f32.f16.f16.f32 "
                 "{%0,%1,%2,%3}, {%4,%5,%6,%7}, {%8,%9}, {%0,%1,%2,%3};"
                 : "+f"(c[0]), "+f"(c[1]), "+f"(c[2]), "+f"(c[3])
                 : "r"(a[0]), "r"(a[1]), "r"(a[2]), "r"(a[3]), "r"(b0), "r"(b1));
}
__device__ __forceinline__ float ex2(float x) {
    float r; asm("ex2.approx.ftz.f32 %0, %1;" : "=f"(r) : "f"(x)); return r;
}
__device__ __forceinline__ void cpa16(void* dst, const void* src) {
    asm volatile("cp.async.cg.shared.global [%0], [%1], 16;"
                 :: "r"((uint32_t)__cvta_generic_to_shared(dst)), "l"(src));
}
__device__ __forceinline__ uint32_t h2u(__half2 v) {
    return *reinterpret_cast<uint32_t*>(&v);
}
// 128B-row XOR swizzle (Swizzle<3,4,3>): bits[4:6] ^= bits[7:9]
__device__ __forceinline__ int swz(int byte_off) {
    return byte_off ^ ((byte_off >> 3) & 0x70);
}

// =====================================================================
// Weight pre-conversion (fp32 -> fp16), once per launch
// =====================================================================
__global__ __launch_bounds__(256) void convert_w_kernel(
        const float* __restrict__ Wq1, const float* __restrict__ Wk1, const float* __restrict__ Wv1,
        const float* __restrict__ Wq2, const float* __restrict__ Wk2, const float* __restrict__ Wv2,
        const float* __restrict__ Wo) {
    const int tid = blockIdx.x * blockDim.x + threadIdx.x;
    const int stride = gridDim.x * blockDim.x;
    const int N1 = DH * HIDDEN;
    const int N2 = HIDDEN * DMODEL;
    for (int i = tid; i < 3 * N1; i += stride) {
        int z = i / N1, j = i - z * N1;
        const float* s = (z == 0) ? Wq1 : (z == 1) ? Wk1 : Wv1;
        g_w1h[z][j] = __float2half(s[j]);
    }
    for (int i = tid; i < 3 * N2; i += stride) {
        int z = i / N2, j = i - z * N2;
        const float* s = (z == 0) ? Wq2 : (z == 1) ? Wk2 : Wv2;
        g_w2h[z][j] = __float2half(s[j]);
    }
    for (int i = tid; i < DMODEL * DH; i += stride)
        g_woh[i] = __float2half(Wo[i]);
}

// =====================================================================
// MLP stage 1: H = relu(X @ W1 + b1)
// =====================================================================
__global__ __launch_bounds__(256) void mlp1_kernel(
        const float* __restrict__ Xq, const float* __restrict__ Xk, const float* __restrict__ Xv,
        const float* __restrict__ bq, const float* __restrict__ bk, const float* __restrict__ bv) {
    __shared__ __half Xs[128][72];
    __shared__ __half Ws[2][64][72];
    const int tid = threadIdx.x, lane = tid & 31, w = tid >> 5;
    const int my = w & 3, wx = w >> 2;
    const int n0 = blockIdx.x * 128, m0 = blockIdx.y * 128, z = blockIdx.z;
    const float* X    = (z == 0) ? Xq : (z == 1) ? Xk : Xv;
    const float* bias = (z == 0) ? bq : (z == 1) ? bk : bv;

    for (int idx = tid; idx < 1024; idx += 256) {
        int r = idx >> 3, c8 = idx & 7;
        const float4* src = (const float4*)(X + (size_t)(m0 + r) * DH + c8 * 8);
        float4 f0 = src[0], f1 = src[1];
        uint4 u;
        u.x = h2u(__floats2half2_rn(f0.x, f0.y));
        u.y = h2u(__floats2half2_rn(f0.z, f0.w));
        u.z = h2u(__floats2half2_rn(f1.x, f1.y));
        u.w = h2u(__floats2half2_rn(f1.z, f1.w));
        *(uint4*)&Xs[r][c8 * 8] = u;
    }
    for (int idx = tid; idx < 1024; idx += 256) {
        int r = idx >> 4, c8 = idx & 15;
        *(uint4*)&Ws[c8 >> 3][r][(c8 & 7) * 8] =
            *(const uint4*)(g_w1h[z] + (size_t)r * HIDDEN + n0 + c8 * 8);
    }
    __syncthreads();

    float acc[2][8][4];
    #pragma unroll
    for (int i = 0; i < 2; i++)
        #pragma unroll
        for (int j = 0; j < 8; j++)
            acc[i][j][0] = acc[i][j][1] = acc[i][j][2] = acc[i][j][3] = 0.0f;

    #pragma unroll
    for (int kk = 0; kk < 4; kk++) {
        uint32_t a[2][4];
        #pragma unroll
        for (int i = 0; i < 2; i++)
            ldsm4(a[i][0], a[i][1], a[i][2], a[i][3],
                  &Xs[my * 32 + i * 16 + (lane & 15)][kk * 16 + 8 * (lane >> 4)]);
        #pragma unroll
        for (int ng = 0; ng < 4; ng++) {
            uint32_t v0, v1, v2, v3;
            ldsm4t(v0, v1, v2, v3,
                   &Ws[wx][kk * 16 + (lane & 7) + 8 * ((lane >> 3) & 1)][ng * 16 + 8 * (lane >> 4)]);
            #pragma unroll
            for (int i = 0; i < 2; i++) {
                mma16816(acc[i][2 * ng],     a[i], v0, v1);
                mma16816(acc[i][2 * ng + 1], a[i], v2, v3);
            }
        }
    }

    const int colbase = n0 + wx * 64;
    #pragma unroll
    for (int j = 0; j < 8; j++) {
        int col = colbase + j * 8 + 2 * (lane & 3);
        float b0 = bias[col], b1 = bias[col + 1];
        #pragma unroll
        for (int i = 0; i < 2; i++) {
            int row = m0 + my * 32 + i * 16 + (lane >> 2);
            *(__half2*)&g_hid[z][(size_t)row * HIDDEN + col] =
                __floats2half2_rn(fmaxf(acc[i][j][0] + b0, 0.f), fmaxf(acc[i][j][1] + b1, 0.f));
            *(__half2*)&g_hid[z][(size_t)(row + 8) * HIDDEN + col] =
                __floats2half2_rn(fmaxf(acc[i][j][2] + b0, 0.f), fmaxf(acc[i][j][3] + b1, 0.f));
        }
    }
}

// =====================================================================
// MLP stage 2: OUT = (H @ W2 + b2) * scale -> [b,h,t,d]
// =====================================================================
__global__ __launch_bounds__(256) void mlp2_kernel(
        const float* __restrict__ bq, const float* __restrict__ bk, const float* __restrict__ bv) {
    extern __shared__ char dynsm[];
    __half (*As)[128][72]    = (__half(*)[128][72])dynsm;
    __half (*Ws)[2][64][72]  = (__half(*)[2][64][72])(dynsm + 36864);
    const int tid = threadIdx.x, lane = tid & 31, w = tid >> 5;
    const int my = w & 3, wx = w >> 2;
    const int nb = blockIdx.x, m0 = blockIdx.y * 128, z = blockIdx.z;
    const float* bias  = (z == 0) ? bq : (z == 1) ? bk : bv;
    const float scale  = (z == 0) ? SCALING : 1.0f;
    const __half* Hsrc = g_hid[z];
    const __half* Wsrc = g_w2h[z];
    const int n0 = nb * 128;

    auto issue = [&](int st, int kc) {
        for (int idx = tid; idx < 1024; idx += 256) {
            int r = idx >> 3, c8 = idx & 7;
            cpa16(&As[st][r][c8 * 8], Hsrc + (size_t)(m0 + r) * HIDDEN + kc * 64 + c8 * 8);
        }
        for (int idx = tid; idx < 1024; idx += 256) {
            int r = idx >> 4, c8 = idx & 15;
            cpa16(&Ws[st][c8 >> 3][r][(c8 & 7) * 8],
                  Wsrc + (size_t)(kc * 64 + r) * DMODEL + n0 + c8 * 8);
        }
        asm volatile("cp.async.commit_group;");
    };

    issue(0, 0);

    float acc[2][8][4];
    #pragma unroll
    for (int i = 0; i < 2; i++)
        #pragma unroll
        for (int j = 0; j < 8; j++)
            acc[i][j][0] = acc[i][j][1] = acc[i][j][2] = acc[i][j][3] = 0.0f;

    for (int kc = 0; kc < 4; kc++) {
        asm volatile("cp.async.wait_group 0;");
        __syncthreads();
        if (kc + 1 < 4) issue((kc + 1) & 1, kc + 1);
        const int cur = kc & 1;
        #pragma unroll
        for (int kk = 0; kk < 4; kk++) {
            uint32_t a[2][4];
            #pragma unroll
            for (int i = 0; i < 2; i++)
                ldsm4(a[i][0], a[i][1], a[i][2], a[i][3],
                      &As[cur][my * 32 + i * 16 + (lane & 15)][kk * 16 + 8 * (lane >> 4)]);
            #pragma unroll
            for (int ng = 0; ng < 4; ng++) {
                uint32_t v0, v1, v2, v3;
                ldsm4t(v0, v1, v2, v3,
                       &Ws[cur][wx][kk * 16 + (lane & 7) + 8 * ((lane >> 3) & 1)][ng * 16 + 8 * (lane >> 4)]);
                #pragma unroll
                for (int i = 0; i < 2; i++) {
                    mma16816(acc[i][2 * ng],     a[i], v0, v1);
                    mma16816(acc[i][2 * ng + 1], a[i], v2, v3);
                }
            }
        }
        __syncthreads();
    }

    __half* dst = (z == 0) ? g_q : (z == 1) ? g_k : g_v;
    const int colbase = n0 + wx * 64;
    #pragma unroll
    for (int j = 0; j < 8; j++) {
        int col = colbase + j * 8 + 2 * (lane & 3);
        float b0 = bias[col], b1 = bias[col + 1];
        int h = col >> 6, d = col & 63;
        #pragma unroll
        for (int i = 0; i < 2; i++) {
            #pragma unroll
            for (int half_ = 0; half_ < 2; half_++) {
                int row = m0 + my * 32 + i * 16 + (lane >> 2) + half_ * 8;
                int t = row >> 2, b = row & 3;
                float v0f = (acc[i][j][2 * half_]     + b0) * scale;
                float v1f = (acc[i][j][2 * half_ + 1] + b1) * scale;
                *(__half2*)&dst[(((size_t)(b * NHEADS + h)) * TSEQ + t) * DH + d] =
                    __floats2half2_rn(v0f, v1f);
            }
        }
    }
}

// =====================================================================
// Flash attention: Br=64, 4 warps, swizzled UNPADDED tiles (8KB each).
// smem = 4 x 8KB = 32KB (Q staged through K[0] buffer at startup),
// so 3 CTAs/SM fit within a ~100KB carveout.
// grid = (8 heads, 32 t-tiles, 4 batch).
// =====================================================================
#define ATTN_SMEM 32768

__global__ __launch_bounds__(128, 3) void attn_kernel(const float* __restrict__ mask) {
    extern __shared__ char sm[];
    // tile buffers: K0, K1, V0, V1 (each 64 rows x 128 bytes, swizzled)
    char* Kb[2] = { sm,          sm + 8192  };
    char* Vb[2] = { sm + 16384,  sm + 24576 };

    const int tid  = threadIdx.x;
    const int lane = tid & 31;
    const int w    = tid >> 5;
    const int h    = blockIdx.x;
    const int t0   = blockIdx.y * 64;
    const int b    = blockIdx.z;

    const __half* qbase = g_q + ((size_t)(b * NHEADS + h) * TSEQ + t0) * DH;
    const __half* kbase = g_k + (size_t)(b * NHEADS + h) * TSEQ * DH;
    const __half* vbase = g_v + (size_t)(b * NHEADS + h) * TSEQ * DH;

    // --- stage Q (64x64 halves = 8KB) into Kb[0], extract fragments ---
    for (int i = tid; i < 512; i += 128) {
        int r = i >> 3, c = i & 7;
        cpa16(Kb[0] + swz(r * 128 + c * 16), qbase + r * 64 + c * 8);
    }
    asm volatile("cp.async.commit_group;");
    asm volatile("cp.async.wait_group 0;");
    __syncthreads();

    uint32_t qa[4][4];
    #pragma unroll
    for (int kk = 0; kk < 4; kk++)
        ldsm4(qa[kk][0], qa[kk][1], qa[kk][2], qa[kk][3],
              Kb[0] + swz((w * 16 + (lane & 15)) * 128 + kk * 32 + 16 * (lane >> 4)));
    __syncthreads();   // Q fragments extracted; Kb[0] reusable

    // --- prologue: K0/V0 ---
    for (int i = tid; i < 512; i += 128) {
        int r = i >> 3, c = i & 7;
        cpa16(Kb[0] + swz(r * 128 + c * 16), kbase + r * 64 + c * 8);
        cpa16(Vb[0] + swz(r * 128 + c * 16), vbase + r * 64 + c * 8);
    }
    asm volatile("cp.async.commit_group;");

    float Oa[8][4];
    #pragma unroll
    for (int j = 0; j < 8; j++) { Oa[j][0] = Oa[j][1] = Oa[j][2] = Oa[j][3] = 0.0f; }
    float m0 = -1e30f, m1 = -1e30f, l0 = 0.0f, l1 = 0.0f;

    const float* mrow = mask + ((size_t)b * TSEQ + (t0 + w * 16 + (lane >> 2))) * TSEQ + 2 * (lane & 3);

    for (int it = 0; it < 32; ++it) {
        const int s0 = it * 64;
        const int cur = it & 1;
        asm volatile("cp.async.wait_group 0;");
        __syncthreads();
        if (it + 1 < 32) {
            const __half* kg = kbase + (size_t)(s0 + 64) * 64;
            const __half* vg = vbase + (size_t)(s0 + 64) * 64;
            const int nxt = cur ^ 1;
            for (int i = tid; i < 512; i += 128) {
                int r = i >> 3, c = i & 7;
                cpa16(Kb[nxt] + swz(r * 128 + c * 16), kg + r * 64 + c * 8);
                cpa16(Vb[nxt] + swz(r * 128 + c * 16), vg + r * 64 + c * 8);
            }
            asm volatile("cp.async.commit_group;");
        }

        float2 mk0[8], mk1[8];
        #pragma unroll
        for (int j = 0; j < 8; j++) {
            mk0[j] = *(const float2*)(mrow + s0 + j * 8);
            mk1[j] = *(const float2*)(mrow + 8 * TSEQ + s0 + j * 8);
        }

        float Sa[8][4];
        #pragma unroll
        for (int j = 0; j < 8; j++) { Sa[j][0] = Sa[j][1] = Sa[j][2] = Sa[j][3] = 0.0f; }
        #pragma unroll
        for (int ng = 0; ng < 4; ng++) {
            #pragma unroll
            for (int kk = 0; kk < 4; kk++) {
                uint32_t k0, k1, k2, k3;
                ldsm4(k0, k1, k2, k3,
                      Kb[cur] + swz((ng * 16 + (lane & 15)) * 128 + kk * 32 + 16 * (lane >> 4)));
                mma16816(Sa[2 * ng],     qa[kk], k0, k2);
                mma16816(Sa[2 * ng + 1], qa[kk], k1, k3);
            }
        }

        float mx0 = -1e30f, mx1 = -1e30f;
        #pragma unroll
        for (int j = 0; j < 8; j++) {
            Sa[j][0] += mk0[j].x; Sa[j][1] += mk0[j].y;
            Sa[j][2] += mk1[j].x; Sa[j][3] += mk1[j].y;
            mx0 = fmaxf(mx0, fmaxf(Sa[j][0], Sa[j][1]));
            mx1 = fmaxf(mx1, fmaxf(Sa[j][2], Sa[j][3]));
        }
        mx0 = fmaxf(mx0, __shfl_xor_sync(0xffffffffu, mx0, 1));
        mx0 = fmaxf(mx0, __shfl_xor_sync(0xffffffffu, mx0, 2));
        mx1 = fmaxf(mx1, __shfl_xor_sync(0xffffffffu, mx1, 1));
        mx1 = fmaxf(mx1, __shfl_xor_sync(0xffffffffu, mx1, 2));
        float mn0 = fmaxf(m0, mx0), mn1 = fmaxf(m1, mx1);
        float alpha0 = ex2((m0 - mn0) * LOG2E);
        float alpha1 = ex2((m1 - mn1) * LOG2E);
        m0 = mn0; m1 = mn1;

        float rs0 = 0.0f, rs1 = 0.0f;
        #pragma unroll
        for (int j = 0; j < 8; j++) {
            Sa[j][0] = ex2((Sa[j][0] - mn0) * LOG2E);
            Sa[j][1] = ex2((Sa[j][1] - mn0) * LOG2E);
            Sa[j][2] = ex2((Sa[j][2] - mn1) * LOG2E);
            Sa[j][3] = ex2((Sa[j][3] - mn1) * LOG2E);
            rs0 += Sa[j][0] + Sa[j][1];
            rs1 += Sa[j][2] + Sa[j][3];
        }
        rs0 += __shfl_xor_sync(0xffffffffu, rs0, 1);
        rs0 += __shfl_xor_sync(0xffffffffu, rs0, 2);
        rs1 += __shfl_xor_sync(0xffffffffu, rs1, 1);
        rs1 += __shfl_xor_sync(0xffffffffu, rs1, 2);
        l0 = l0 * alpha0 + rs0;
        l1 = l1 * alpha1 + rs1;

        uint32_t Pa[4][4];
        #pragma unroll
        for (int kk = 0; kk < 4; kk++) {
            Pa[kk][0] = h2u(__floats2half2_rn(Sa[2 * kk][0],     Sa[2 * kk][1]));
            Pa[kk][1] = h2u(__floats2half2_rn(Sa[2 * kk][2],     Sa[2 * kk][3]));
            Pa[kk][2] = h2u(__floats2half2_rn(Sa[2 * kk + 1][0], Sa[2 * kk + 1][1]));
            Pa[kk][3] = h2u(__floats2half2_rn(Sa[2 * kk + 1][2], Sa[2 * kk + 1][3]));
        }

        #pragma unroll
        for (int j = 0; j < 8; j++) {
            Oa[j][0] *= alpha0; Oa[j][1] *= alpha0;
            Oa[j][2] *= alpha1; Oa[j][3] *= alpha1;
        }

        #pragma unroll
        for (int kk = 0; kk < 4; kk++) {
            #pragma unroll
            for (int ng = 0; ng < 4; ng++) {
                uint32_t v0, v1, v2, v3;
                ldsm4t(v0, v1, v2, v3,
                       Vb[cur] + swz((kk * 16 + (lane & 7) + 8 * ((lane >> 3) & 1)) * 128
                                     + ng * 32 + 16 * (lane >> 4)));
                mma16816(Oa[2 * ng],     Pa[kk], v0, v1);
                mma16816(Oa[2 * ng + 1], Pa[kk], v2, v3);
            }
        }
    }

    const float inv0 = 1.0f / l0, inv1 = 1.0f / l1;
    const int r0g = t0 + w * 16 + (lane >> 2);
    const int r1g = r0g + 8;
    #pragma unroll
    for (int j = 0; j < 8; j++) {
        int col = h * DH + j * 8 + 2 * (lane & 3);
        __half2* p0 = (__half2*)(g_ao + ((size_t)r0g * BATCH + b) * DMODEL + col);
        __half2* p1 = (__half2*)(g_ao + ((size_t)r1g * BATCH + b) * DMODEL + col);
        *p0 = __floats2half2_rn(Oa[j][0] * inv0, Oa[j][1] * inv0);
        *p1 = __floats2half2_rn(Oa[j][2] * inv1, Oa[j][3] * inv1);
    }
}

// =====================================================================
// Output projection: OUT[8192,64] = AO[8192,512] @ Wo + bo
// =====================================================================
__global__ __launch_bounds__(256) void oproj_kernel(const float* __restrict__ bias,
                                                    float* __restrict__ out) {
    __shared__ __half As[2][64][72];
    __shared__ __half Ws[2][64][72];
    const int tid = threadIdx.x, lane = tid & 31, w = tid >> 5;
    const int my = w & 3, wn = w >> 2;
    const int m0 = blockIdx.x * 64;

    auto issue = [&](int st, int kc) {
        for (int idx = tid; idx < 512; idx += 256) {
            int r = idx >> 3, c8 = idx & 7;
            cpa16(&As[st][r][c8 * 8], g_ao + (size_t)(m0 + r) * DMODEL + kc * 64 + c8 * 8);
        }
        for (int idx = tid; idx < 512; idx += 256) {
            int r = idx >> 3, c8 = idx & 7;
            cpa16(&Ws[st][r][c8 * 8], g_woh + (size_t)(kc * 64 + r) * DH + c8 * 8);
        }
        asm volatile("cp.async.commit_group;");
    };

    issue(0, 0);

    float acc[4][4];
    #pragma unroll
    for (int j = 0; j < 4; j++) acc[j][0] = acc[j][1] = acc[j][2] = acc[j][3] = 0.0f;

    for (int kc = 0; kc < 8; kc++) {
        asm volatile("cp.async.wait_group 0;");
        __syncthreads();
        if (kc + 1 < 8) issue((kc + 1) & 1, kc + 1);
        const int cur = kc & 1;
        #pragma unroll
        for (int kk = 0; kk < 4; kk++) {
            uint32_t a[4];
            ldsm4(a[0], a[1], a[2], a[3],
                  &As[cur][my * 16 + (lane & 15)][kk * 16 + 8 * (lane >> 4)]);
            #pragma unroll
            for (int ng = 0; ng < 2; ng++) {
                uint32_t v0, v1, v2, v3;
                ldsm4t(v0, v1, v2, v3,
                       &Ws[cur][kk * 16 + (lane & 7) + 8 * ((lane >> 3) & 1)][wn * 32 + ng * 16 + 8 * (lane >> 4)]);
                mma16816(acc[2 * ng],     a, v0, v1);
                mma16816(acc[2 * ng + 1], a, v2, v3);
            }
        }
        __syncthreads();
    }

    #pragma unroll
    for (int j = 0; j < 4; j++) {
        int col = wn * 32 + j * 8 + 2 * (lane & 3);
        float b0 = bias[col], b1 = bias[col + 1];
        int row = m0 + my * 16 + (lane >> 2);
        *(float2*)&out[(size_t)row * DH + col]       = make_float2(acc[j][0] + b0, acc[j][1] + b1);
        *(float2*)&out[(size_t)(row + 8) * DH + col] = make_float2(acc[j][2] + b0, acc[j][3] + b1);
    }
}

// =====================================================================
extern "C" void kernel_launch(void* const* d_in, const int* in_sizes, int n_in,
                              void* d_out, int out_size) {
    const float* query = (const float*)d_in[0];
    const float* key   = (const float*)d_in[1];
    const float* value = (const float*)d_in[2];
    const float* amask = (const float*)d_in[3];
    const float* Wq1 = (const float*)d_in[4];
    const float* bq1 = (const float*)d_in[5];
    const float* Wq2 = (const float*)d_in[6];
    const float* bq2 = (const float*)d_in[7];
    const float* Wk1 = (const float*)d_in[8];
    const float* bk1 = (const float*)d_in[9];
    const float* Wk2 = (const float*)d_in[10];
    const float* bk2 = (const float*)d_in[11];
    const float* Wv1 = (const float*)d_in[12];
    const float* bv1 = (const float*)d_in[13];
    const float* Wv2 = (const float*)d_in[14];
    const float* bv2 = (const float*)d_in[15];
    const float* Wo  = (const float*)d_in[16];
    const float* bo  = (const float*)d_in[17];
    float* out = (float*)d_out;

    convert_w_kernel<<<512, 256>>>(Wq1, Wk1, Wv1, Wq2, Wk2, Wv2, Wo);
    mlp1_kernel<<<dim3(2, 64, 3), 256>>>(query, key, value, bq1, bk1, bv1);
    cudaFuncSetAttribute(mlp2_kernel, cudaFuncAttributeMaxDynamicSharedMemorySize, 73728);
    mlp2_kernel<<<dim3(4, 64, 3), 256, 73728>>>(bq2, bk2, bv2);
    cudaFuncSetAttribute(attn_kernel, cudaFuncAttributeMaxDynamicSharedMemorySize, ATTN_SMEM);
    cudaFuncSetAttribute(attn_kernel, cudaFuncAttributePreferredSharedMemoryCarveout, 100);
    attn_kernel<<<dim3(NHEADS, TSEQ / 64, BATCH), 128, ATTN_SMEM>>>(amask);
    oproj_kernel<<<dim3(128), 256>>>(bo, out);
}